// round 1
// baseline (speedup 1.0000x reference)
#include <cuda_runtime.h>
#include <cuda_bf16.h>
#include <cstdint>

#define DIM   129
#define NC    8193            // N_CTX + 1
#define NSEQ  8192
#define LMBD  0.9f
#define INVN  (1.0f/8192.0f)
#define LDE   8224            // padded leading dim for expX (multiple of 32 floats)
#define SPAD  8208            // padded rows for s_part
#define NTC   129             // number of 64-wide column tiles over 8193
#define SZ    (DIM*NC)

// ---------------- device scratch (static; no runtime allocation) ----------------
__device__ float g_W[SZ];                       // Q @ Z
__device__ float g_Y[SZ];                       // P @ Z
__device__ float g_T[SZ];                       // (P@Z) @ M  via backward scan
__device__ float g_sinv[NC];                    // 1 / rowsum(exp(X))
__device__ float g_spart[(size_t)NTC * SPAD];   // deterministic partial row sums
__device__ float g_expX[(size_t)NC * LDE];      // exp(X), ~270 MB
__device__ float g_Za[SZ], g_Zb[SZ];            // layer ping-pong
__device__ float g_Upart[(size_t)4 * SZ];       // K-split partials for U GEMM

// ---------------- kernel 1: W = Q@Z, Y = P@Z ----------------
__global__ __launch_bounds__(256) void kernel_qp(const float* __restrict__ Zin,
                                                 const float* __restrict__ Q,
                                                 const float* __restrict__ P) {
    __shared__ float Zs[DIM][64];
    const int c0  = blockIdx.x * 64;
    const int tid = threadIdx.x;
    const int c   = tid & 63;
    const int g   = tid >> 6;           // 0..3
    for (int k = g; k < DIM; k += 4)
        Zs[k][c] = (c0 + c < NC) ? Zin[(size_t)k * NC + c0 + c] : 0.f;
    __syncthreads();
    if (c0 + c < NC) {
        for (int d = g; d < DIM; d += 4) {
            float aw = 0.f, ay = 0.f;
            const float* qrow = Q + (size_t)d * DIM;
            const float* prow = P + (size_t)d * DIM;
            #pragma unroll 8
            for (int k = 0; k < DIM; k++) {
                float z = Zs[k][c];
                aw = fmaf(qrow[k], z, aw);
                ay = fmaf(prow[k], z, ay);
            }
            g_W[(size_t)d * NC + c0 + c] = aw;
            g_Y[(size_t)d * NC + c0 + c] = ay;
        }
    }
}

// ---------------- kernel 2: backward decayed scan  T[j] = Y[j] + lam*T[j+1], T[8192]=0 ----
__global__ __launch_bounds__(256) void kernel_scan() {
    const int r = blockIdx.x;                 // row d of Y/T, 0..128
    const int t = threadIdx.x;                // 256 threads, 32 elems each -> 8192
    const float* Y = g_Y + (size_t)r * NC;
    float*       T = g_T + (size_t)r * NC;
    const int base = t * 32;

    float s = 0.f;
    #pragma unroll
    for (int u = 31; u >= 0; u--) s = fmaf(s, LMBD, Y[base + u]);

    __shared__ float C[256];
    C[t] = s;
    __syncthreads();

    float f = 1.f;
    #pragma unroll
    for (int i = 0; i < 32; i++) f *= LMBD;   // lam^32

    for (int off = 1; off < 256; off <<= 1) {
        float add = (t + off < 256) ? C[t + off] * f : 0.f;
        __syncthreads();
        C[t] += add;
        __syncthreads();
        f *= f;
    }
    float cur = (t < 255) ? C[t + 1] : 0.f;   // T at segment end boundary
    #pragma unroll
    for (int u = 31; u >= 0; u--) {
        cur = fmaf(LMBD, cur, Y[base + u]);
        T[base + u] = cur;
    }
    if (t == 0) T[NSEQ] = 0.f;
}

// ---------------- kernel 3: X = Z^T W (64x64 tiles), store exp(X), partial row sums ----
#define XBK 16
__global__ __launch_bounds__(256) void kernel_x(const float* __restrict__ Zin) {
    __shared__ float As[XBK][64];
    __shared__ float Bs[XBK][64];
    const int r0 = blockIdx.y * 64;
    const int c0 = blockIdx.x * 64;
    const int tid = threadIdx.x;
    const int tx = tid & 15, ty = tid >> 4;
    const int lm = tid & 63, lk = tid >> 6;

    float acc[4][4] = {};
    for (int kk = 0; kk < DIM; kk += XBK) {
        #pragma unroll
        for (int i = 0; i < 4; i++) {
            int k  = lk + i * 4;
            int kg = kk + k;
            bool kv = (kg < DIM);
            As[k][lm] = (kv && r0 + lm < NC) ? Zin[(size_t)kg * NC + r0 + lm] : 0.f;
            Bs[k][lm] = (kv && c0 + lm < NC) ? g_W[(size_t)kg * NC + c0 + lm] : 0.f;
        }
        __syncthreads();
        #pragma unroll
        for (int k = 0; k < XBK; k++) {
            float4 a4 = *reinterpret_cast<const float4*>(&As[k][ty * 4]);
            float4 b4 = *reinterpret_cast<const float4*>(&Bs[k][tx * 4]);
            float av[4] = {a4.x, a4.y, a4.z, a4.w};
            float bv[4] = {b4.x, b4.y, b4.z, b4.w};
            #pragma unroll
            for (int i = 0; i < 4; i++)
                #pragma unroll
                for (int j = 0; j < 4; j++)
                    acc[i][j] = fmaf(av[i], bv[j], acc[i][j]);
        }
        __syncthreads();
    }

    // epilogue: exp + store + per-row partial sums over this 64-col tile
    float rsum[4] = {0.f, 0.f, 0.f, 0.f};
    const bool cfull = (c0 + 64 <= NC);
    #pragma unroll
    for (int i = 0; i < 4; i++) {
        int r = r0 + ty * 4 + i;
        if (r >= NC) continue;
        float e[4];
        #pragma unroll
        for (int j = 0; j < 4; j++) e[j] = __expf(acc[i][j]);
        if (cfull) {
            float4 v = make_float4(e[0], e[1], e[2], e[3]);
            *reinterpret_cast<float4*>(&g_expX[(size_t)r * LDE + c0 + tx * 4]) = v;
            rsum[i] = e[0] + e[1] + e[2] + e[3];
        } else {
            #pragma unroll
            for (int j = 0; j < 4; j++) {
                int c = c0 + tx * 4 + j;
                if (c < NC) {
                    g_expX[(size_t)r * LDE + c] = e[j];
                    rsum[i] += e[j];
                }
            }
        }
    }
    #pragma unroll
    for (int i = 0; i < 4; i++) {
        float v = rsum[i];
        #pragma unroll
        for (int o = 8; o; o >>= 1) v += __shfl_xor_sync(0xffffffffu, v, o, 16);
        if (tx == 0) {
            int r = r0 + ty * 4 + i;
            if (r < NC) g_spart[(size_t)blockIdx.x * SPAD + r] = v;
        }
    }
}

// ---------------- kernel 4: s[r] = sum of partials (fixed order), store 1/s ----------
__global__ __launch_bounds__(256) void kernel_s() {
    int r = blockIdx.x * 256 + threadIdx.x;
    if (r < NC) {
        float s = 0.f;
        #pragma unroll 8
        for (int t = 0; t < NTC; t++) s += g_spart[(size_t)t * SPAD + r];
        g_sinv[r] = 1.0f / s;
    }
}

// ---------------- kernel 5: U = (T * diag(sinv)) @ expX, K-split x4 -----------------
#define UBK 16
__global__ __launch_bounds__(256) void kernel_u() {
    __shared__ float As[48][UBK + 1];   // [m][k]
    __shared__ float Bs[UBK][64];
    const int c0 = blockIdx.x * 64;
    const int m0 = blockIdx.y * 48;
    const int kz = blockIdx.z;
    const int rbeg = kz * 2048;
    const int rend = min(rbeg + 2048, NC);   // kz==3 covers 2049
    const int tid = threadIdx.x;
    const int tx = tid & 15, ty = tid >> 4;
    const int lk = tid & 15, lm = tid >> 4;  // A loader
    const int bn = tid & 63, bk = tid >> 6;  // B loader

    float acc[3][4] = {};
    for (int rr = rbeg; rr < rend; rr += UBK) {
        #pragma unroll
        for (int i = 0; i < 3; i++) {
            int m = lm + i * 16;
            int k = rr + lk;
            As[m][lk] = (m0 + m < DIM && k < rend)
                        ? g_T[(size_t)(m0 + m) * NC + k] * g_sinv[k] : 0.f;
        }
        #pragma unroll
        for (int i = 0; i < 4; i++) {
            int k = bk + i * 4;
            Bs[k][bn] = (rr + k < rend && c0 + bn < NC)
                        ? g_expX[(size_t)(rr + k) * LDE + c0 + bn] : 0.f;
        }
        __syncthreads();
        #pragma unroll
        for (int k = 0; k < UBK; k++) {
            float4 b4 = *reinterpret_cast<const float4*>(&Bs[k][tx * 4]);
            float bv[4] = {b4.x, b4.y, b4.z, b4.w};
            #pragma unroll
            for (int i = 0; i < 3; i++) {
                float a = As[ty * 3 + i][k];
                #pragma unroll
                for (int j = 0; j < 4; j++)
                    acc[i][j] = fmaf(a, bv[j], acc[i][j]);
            }
        }
        __syncthreads();
    }
    float* U = g_Upart + (size_t)kz * SZ;
    #pragma unroll
    for (int i = 0; i < 3; i++) {
        int d = m0 + ty * 3 + i;
        if (d >= DIM) continue;
        #pragma unroll
        for (int j = 0; j < 4; j++) {
            int c = c0 + tx * 4 + j;
            if (c < NC) U[(size_t)d * NC + c] = acc[i][j];
        }
    }
}

// ---------------- kernel 6: Zout = Zin + invn * sum(Upart) --------------------------
__global__ __launch_bounds__(256) void kernel_fin(const float* __restrict__ Zin,
                                                  float* __restrict__ Zout) {
    int i = blockIdx.x * 256 + threadIdx.x;
    if (i < SZ) {
        float u = g_Upart[i] + g_Upart[(size_t)SZ + i]
                + g_Upart[(size_t)2 * SZ + i] + g_Upart[(size_t)3 * SZ + i];
        Zout[i] = fmaf(INVN, u, Zin[i]);
    }
}

// ---------------- launch ----------------
extern "C" void kernel_launch(void* const* d_in, const int* in_sizes, int n_in,
                              void* d_out, int out_size) {
    const float* Z = (const float*)d_in[0];   // (129, 8193)
    const float* P = (const float*)d_in[1];   // (129, 129)
    const float* Q = (const float*)d_in[2];   // (129, 129)
    float* out = (float*)d_out;

    float* za; float* zb;
    cudaGetSymbolAddress((void**)&za, g_Za);
    cudaGetSymbolAddress((void**)&zb, g_Zb);

    const float* zin;
    float* zout;
    for (int l = 0; l < 4; l++) {
        if (l == 0)      { zin = Z;  zout = za; }
        else if (l == 1) { zin = za; zout = zb; }
        else if (l == 2) { zin = zb; zout = za; }
        else             { zin = za; zout = out; }

        kernel_qp  <<<129, 256>>>(zin, Q, P);
        kernel_scan<<<DIM, 256>>>();
        kernel_x   <<<dim3(NTC, NTC), 256>>>(zin);
        kernel_s   <<<(NC + 255) / 256, 256>>>();
        kernel_u   <<<dim3(NTC, 3, 4), 256>>>();
        kernel_fin <<<(SZ + 255) / 256, 256>>>(zin, zout);
    }
}

// round 4
// speedup vs baseline: 2.5231x; 2.5231x over previous
#include <cuda_runtime.h>
#include <cuda_bf16.h>
#include <cstdint>

#define DIM   129
#define NC    8193
#define NSEQ  8192
#define NCP   8320          // 65 * 128
#define KP    144           // DIM padded to multiple of 16
#define LDK   26            // smem k-pitch (halves) for kernel_x
#define LDKU  34            // smem k-pitch (halves) for kernel_u (32-chunk)
#define UCH   32
#define NKCH  (NCP/UCH)     // 260
#define NTC   65
#define LMBD  0.9f
#define INVN  (1.0f/8192.0f)
#define SZ    (DIM*NC)

// ---------------- device scratch ----------------
__device__ __align__(16) uint16_t g_Zbf[(size_t)KP * NCP];    // Z bf16 bits, [k][m], zero-padded
__device__ __align__(16) uint16_t g_Wbf[(size_t)KP * NCP];    // Q@Z bf16 bits, [d][c], zero-padded
__device__ __align__(16) uint16_t g_Tbf[(size_t)KP * NCP];    // (T*sinv) bf16 bits, [m][k], zero-padded
__device__ __align__(16) uint16_t g_Eb [(size_t)NCP * NCP];   // exp(X) bf16 bits, [r][c]  (~138 MB)
__device__ float    g_Y[SZ];
__device__ float    g_T[SZ];
__device__ float    g_sinv[NC];
__device__ float    g_spart[(size_t)NTC * NCP];
__device__ float    g_ZA[SZ], g_ZB[SZ];

__device__ __forceinline__ void mma16816(float* d, const uint32_t* a, const uint32_t* b) {
    asm volatile(
        "mma.sync.aligned.m16n8k16.row.col.f32.bf16.bf16.f32 "
        "{%0,%1,%2,%3},{%4,%5,%6,%7},{%8,%9},{%0,%1,%2,%3};\n"
        : "+f"(d[0]), "+f"(d[1]), "+f"(d[2]), "+f"(d[3])
        : "r"(a[0]), "r"(a[1]), "r"(a[2]), "r"(a[3]), "r"(b[0]), "r"(b[1]));
}

__device__ __forceinline__ uint16_t f2bf(float x) {
    __nv_bfloat16 h = __float2bfloat16(x);
    return reinterpret_cast<uint16_t&>(h);
}

// ---------------- init: zero the padded bf16 operand buffers ----------------
__global__ void kernel_init() {
    size_t n = (size_t)KP * NCP;
    size_t stride = (size_t)gridDim.x * blockDim.x;
    for (size_t j = (size_t)blockIdx.x * blockDim.x + threadIdx.x; j < n; j += stride) {
        g_Zbf[j] = 0; g_Wbf[j] = 0; g_Tbf[j] = 0;
    }
}

// ---------------- kernel 1: W = Q@Z (bf16 out), Y = P@Z (fp32), Zb = bf16(Z) ----------
__global__ __launch_bounds__(256) void kernel_qp(const float* __restrict__ Zin,
                                                 const float* __restrict__ Q,
                                                 const float* __restrict__ P) {
    __shared__ float Zs[DIM][64];
    const int c0 = blockIdx.x * 64;
    const int tid = threadIdx.x;
    const int c = tid & 63;
    const int grp = tid >> 6;
    for (int k = grp; k < DIM; k += 4) {
        float z = (c0 + c < NC) ? Zin[(size_t)k * NC + c0 + c] : 0.f;
        Zs[k][c] = z;
        if (c0 + c < NC) g_Zbf[(size_t)k * NCP + c0 + c] = f2bf(z);
    }
    __syncthreads();
    if (c0 + c < NC) {
        for (int d = grp; d < DIM; d += 4) {
            float aw = 0.f, ay = 0.f;
            const float* qrow = Q + (size_t)d * DIM;
            const float* prow = P + (size_t)d * DIM;
            #pragma unroll 8
            for (int k = 0; k < DIM; k++) {
                float z = Zs[k][c];
                aw = fmaf(qrow[k], z, aw);
                ay = fmaf(prow[k], z, ay);
            }
            g_Wbf[(size_t)d * NCP + c0 + c] = f2bf(aw);
            g_Y[(size_t)d * NC + c0 + c] = ay;
        }
    }
}

// ---------------- kernel 2: backward decayed scan T[j] = Y[j] + lam*T[j+1] ----------
__global__ __launch_bounds__(256) void kernel_scan() {
    const int r = blockIdx.x;
    const int t = threadIdx.x;
    const float* Y = g_Y + (size_t)r * NC;
    float*       T = g_T + (size_t)r * NC;
    const int base = t * 32;

    float s = 0.f;
    #pragma unroll
    for (int u = 31; u >= 0; u--) s = fmaf(s, LMBD, Y[base + u]);

    __shared__ float C[256];
    C[t] = s;
    __syncthreads();

    float f = 1.f;
    #pragma unroll
    for (int i = 0; i < 32; i++) f *= LMBD;

    for (int off = 1; off < 256; off <<= 1) {
        float add = (t + off < 256) ? C[t + off] * f : 0.f;
        __syncthreads();
        C[t] += add;
        __syncthreads();
        f *= f;
    }
    float cur = (t < 255) ? C[t + 1] : 0.f;
    #pragma unroll
    for (int u = 31; u >= 0; u--) {
        cur = fmaf(LMBD, cur, Y[base + u]);
        T[base + u] = cur;
    }
    if (t == 0) T[NSEQ] = 0.f;
}

// ---------------- kernel 3: X = Z^T W via bf16 HMMA, exp + store Eb + row partials ----
__global__ __launch_bounds__(256) void kernel_x() {
    __shared__ __align__(16) uint16_t As[2][128 * LDK];
    __shared__ __align__(16) uint16_t Bs[2][128 * LDK];
    __shared__ float Ssum[4][128];
    const int bx = blockIdx.x, by = blockIdx.y;
    const int r0 = by * 128, c0 = bx * 128;
    const int tid = threadIdx.x, lane = tid & 31, wid = tid >> 5;
    const int wm = wid >> 2, wn = wid & 3, g = lane >> 2, t = lane & 3;

    float acc[4][4][4];
    #pragma unroll
    for (int i = 0; i < 4; i++)
        #pragma unroll
        for (int j = 0; j < 4; j++)
            #pragma unroll
            for (int q = 0; q < 4; q++) acc[i][j][q] = 0.f;

    // prologue: stage chunk 0
    {
        #pragma unroll
        for (int i = 0; i < 4; i++) {
            int u = tid + 256 * i;
            int k = u >> 6, np = u & 63;
            uint32_t va = *reinterpret_cast<const uint32_t*>(&g_Zbf[(size_t)k * NCP + r0 + 2 * np]);
            As[0][(2 * np) * LDK + k] = (uint16_t)va;
            As[0][(2 * np + 1) * LDK + k] = (uint16_t)(va >> 16);
            uint32_t vb = *reinterpret_cast<const uint32_t*>(&g_Wbf[(size_t)k * NCP + c0 + 2 * np]);
            Bs[0][(2 * np) * LDK + k] = (uint16_t)vb;
            Bs[0][(2 * np + 1) * LDK + k] = (uint16_t)(vb >> 16);
        }
    }
    __syncthreads();

    #pragma unroll
    for (int ck = 0; ck < 9; ck++) {
        const int cur = ck & 1;
        uint32_t va[4], vb[4];
        if (ck < 8) {
            const int kk = (ck + 1) * 16;
            #pragma unroll
            for (int i = 0; i < 4; i++) {
                int u = tid + 256 * i;
                int k = u >> 6, np = u & 63;
                va[i] = *reinterpret_cast<const uint32_t*>(&g_Zbf[(size_t)(kk + k) * NCP + r0 + 2 * np]);
                vb[i] = *reinterpret_cast<const uint32_t*>(&g_Wbf[(size_t)(kk + k) * NCP + c0 + 2 * np]);
            }
        }
        const uint32_t* A32 = reinterpret_cast<const uint32_t*>(As[cur]);
        const uint32_t* B32 = reinterpret_cast<const uint32_t*>(Bs[cur]);
        uint32_t a[4][4], b[4][2];
        #pragma unroll
        for (int mf = 0; mf < 4; mf++) {
            int rb = wm * 64 + mf * 16;
            a[mf][0] = A32[((rb + g) * LDK + 2 * t) >> 1];
            a[mf][1] = A32[((rb + g + 8) * LDK + 2 * t) >> 1];
            a[mf][2] = A32[((rb + g) * LDK + 2 * t + 8) >> 1];
            a[mf][3] = A32[((rb + g + 8) * LDK + 2 * t + 8) >> 1];
        }
        #pragma unroll
        for (int nf = 0; nf < 4; nf++) {
            int cb = wn * 32 + nf * 8;
            b[nf][0] = B32[((cb + g) * LDK + 2 * t) >> 1];
            b[nf][1] = B32[((cb + g) * LDK + 2 * t + 8) >> 1];
        }
        #pragma unroll
        for (int mf = 0; mf < 4; mf++)
            #pragma unroll
            for (int nf = 0; nf < 4; nf++)
                mma16816(acc[mf][nf], a[mf], b[nf]);

        if (ck < 8) {
            __syncthreads();
            const int s = cur ^ 1;
            #pragma unroll
            for (int i = 0; i < 4; i++) {
                int u = tid + 256 * i;
                int k = u >> 6, np = u & 63;
                As[s][(2 * np) * LDK + k] = (uint16_t)va[i];
                As[s][(2 * np + 1) * LDK + k] = (uint16_t)(va[i] >> 16);
                Bs[s][(2 * np) * LDK + k] = (uint16_t)vb[i];
                Bs[s][(2 * np + 1) * LDK + k] = (uint16_t)(vb[i] >> 16);
            }
            __syncthreads();
        }
    }

    // epilogue: exp, store bf16, masked row partial sums
    float rs[4][2];
    #pragma unroll
    for (int mf = 0; mf < 4; mf++) { rs[mf][0] = 0.f; rs[mf][1] = 0.f; }
    #pragma unroll
    for (int mf = 0; mf < 4; mf++) {
        int rg = r0 + wm * 64 + mf * 16 + g;
        #pragma unroll
        for (int nf = 0; nf < 4; nf++) {
            int cb = c0 + wn * 32 + nf * 8 + 2 * t;
            float e0 = __expf(acc[mf][nf][0]);
            float e1 = __expf(acc[mf][nf][1]);
            float e2 = __expf(acc[mf][nf][2]);
            float e3 = __expf(acc[mf][nf][3]);
            __nv_bfloat162 p01 = __floats2bfloat162_rn(e0, e1);
            __nv_bfloat162 p23 = __floats2bfloat162_rn(e2, e3);
            *reinterpret_cast<uint32_t*>(&g_Eb[(size_t)rg * NCP + cb]) = reinterpret_cast<uint32_t&>(p01);
            *reinterpret_cast<uint32_t*>(&g_Eb[(size_t)(rg + 8) * NCP + cb]) = reinterpret_cast<uint32_t&>(p23);
            float m0 = (cb < NC) ? 1.f : 0.f;
            float m1 = (cb + 1 < NC) ? 1.f : 0.f;
            rs[mf][0] += e0 * m0 + e1 * m1;
            rs[mf][1] += e2 * m0 + e3 * m1;
        }
    }
    #pragma unroll
    for (int mf = 0; mf < 4; mf++)
        #pragma unroll
        for (int h = 0; h < 2; h++) {
            float v = rs[mf][h];
            v += __shfl_xor_sync(0xffffffffu, v, 1);
            v += __shfl_xor_sync(0xffffffffu, v, 2);
            rs[mf][h] = v;
        }
    if (t == 0) {
        #pragma unroll
        for (int mf = 0; mf < 4; mf++) {
            Ssum[wn][wm * 64 + mf * 16 + g]     = rs[mf][0];
            Ssum[wn][wm * 64 + mf * 16 + g + 8] = rs[mf][1];
        }
    }
    __syncthreads();
    if (tid < 128) {
        float p = Ssum[0][tid] + Ssum[1][tid] + Ssum[2][tid] + Ssum[3][tid];
        g_spart[(size_t)bx * NCP + r0 + tid] = p;
    }
}

// ---------------- kernel 4: sinv ----------------
__global__ __launch_bounds__(256) void kernel_s() {
    int r = blockIdx.x * 256 + threadIdx.x;
    if (r < NC) {
        float s = 0.f;
        #pragma unroll 5
        for (int tb = 0; tb < NTC; tb++) s += g_spart[(size_t)tb * NCP + r];
        g_sinv[r] = 1.0f / s;
    }
}

// ---------------- kernel 5: Tb = bf16(T * sinv) ----------------
__global__ __launch_bounds__(256) void kernel_tb() {
    int k = blockIdx.x * 256 + threadIdx.x;
    int m = blockIdx.y;
    if (k < NC) {
        float v = g_T[(size_t)m * NC + k] * g_sinv[k];
        g_Tbf[(size_t)m * NCP + k] = f2bf(v);
    }
}

// ---------------- kernel 6: Zout = Zin + invn * (Tb @ Eb), bf16 HMMA ----------------
__global__ __launch_bounds__(384) void kernel_u(const float* __restrict__ Zin,
                                                float* __restrict__ Zout) {
    __shared__ __align__(16) uint16_t As[2][KP * LDKU];
    __shared__ __align__(16) uint16_t Bs[2][64 * LDKU];
    const int c0 = blockIdx.x * 64;
    const int tid = threadIdx.x, lane = tid & 31, wid = tid >> 5;
    const int wm = wid >> 2, wn = wid & 3, g = lane >> 2, t = lane & 3;

    float acc[3][2][4];
    #pragma unroll
    for (int i = 0; i < 3; i++)
        #pragma unroll
        for (int j = 0; j < 2; j++)
            #pragma unroll
            for (int q = 0; q < 4; q++) acc[i][j][q] = 0.f;

    // prologue stage chunk 0
    {
        #pragma unroll
        for (int i = 0; i < 6; i++) {
            int u = tid + 384 * i;
            int m = u >> 4, kq = u & 15;
            *reinterpret_cast<uint32_t*>(&As[0][m * LDKU + 2 * kq]) =
                *reinterpret_cast<const uint32_t*>(&g_Tbf[(size_t)m * NCP + 2 * kq]);
        }
        #pragma unroll
        for (int i = 0; i < 3; i++) {
            int u = tid + 384 * i;
            if (u < 1024) {
                int k = u >> 5, np = u & 31;
                uint32_t v = *reinterpret_cast<const uint32_t*>(&g_Eb[(size_t)k * NCP + c0 + 2 * np]);
                Bs[0][(2 * np) * LDKU + k] = (uint16_t)v;
                Bs[0][(2 * np + 1) * LDKU + k] = (uint16_t)(v >> 16);
            }
        }
    }
    __syncthreads();

    for (int ck = 0; ck < NKCH; ck++) {
        const int cur = ck & 1;
        uint32_t va[6], vb[3];
        if (ck + 1 < NKCH) {
            const int kk = (ck + 1) * UCH;
            #pragma unroll
            for (int i = 0; i < 6; i++) {
                int u = tid + 384 * i;
                int m = u >> 4, kq = u & 15;
                va[i] = *reinterpret_cast<const uint32_t*>(&g_Tbf[(size_t)m * NCP + kk + 2 * kq]);
            }
            #pragma unroll
            for (int i = 0; i < 3; i++) {
                int u = tid + 384 * i;
                vb[i] = (u < 1024)
                    ? *reinterpret_cast<const uint32_t*>(&g_Eb[(size_t)(kk + (u >> 5)) * NCP + c0 + 2 * (u & 31)])
                    : 0u;
            }
        }
        const uint32_t* A32 = reinterpret_cast<const uint32_t*>(As[cur]);
        const uint32_t* B32 = reinterpret_cast<const uint32_t*>(Bs[cur]);
        #pragma unroll
        for (int ks = 0; ks < 2; ks++) {
            const int ko = ks * 16;
            uint32_t a[3][4], b[2][2];
            #pragma unroll
            for (int mf = 0; mf < 3; mf++) {
                int rb = wm * 48 + mf * 16;
                a[mf][0] = A32[((rb + g) * LDKU + ko + 2 * t) >> 1];
                a[mf][1] = A32[((rb + g + 8) * LDKU + ko + 2 * t) >> 1];
                a[mf][2] = A32[((rb + g) * LDKU + ko + 2 * t + 8) >> 1];
                a[mf][3] = A32[((rb + g + 8) * LDKU + ko + 2 * t + 8) >> 1];
            }
            #pragma unroll
            for (int nf = 0; nf < 2; nf++) {
                int cb = wn * 16 + nf * 8;
                b[nf][0] = B32[((cb + g) * LDKU + ko + 2 * t) >> 1];
                b[nf][1] = B32[((cb + g) * LDKU + ko + 2 * t + 8) >> 1];
            }
            #pragma unroll
            for (int mf = 0; mf < 3; mf++)
                #pragma unroll
                for (int nf = 0; nf < 2; nf++)
                    mma16816(acc[mf][nf], a[mf], b[nf]);
        }
        if (ck + 1 < NKCH) {
            __syncthreads();
            const int s = cur ^ 1;
            #pragma unroll
            for (int i = 0; i < 6; i++) {
                int u = tid + 384 * i;
                int m = u >> 4, kq = u & 15;
                *reinterpret_cast<uint32_t*>(&As[s][m * LDKU + 2 * kq]) = va[i];
            }
            #pragma unroll
            for (int i = 0; i < 3; i++) {
                int u = tid + 384 * i;
                if (u < 1024) {
                    int k = u >> 5, np = u & 31;
                    Bs[s][(2 * np) * LDKU + k] = (uint16_t)vb[i];
                    Bs[s][(2 * np + 1) * LDKU + k] = (uint16_t)(vb[i] >> 16);
                }
            }
            __syncthreads();
        }
    }

    // epilogue: residual + scale
    #pragma unroll
    for (int mf = 0; mf < 3; mf++) {
        int m = wm * 48 + mf * 16 + g;
        #pragma unroll
        for (int nf = 0; nf < 2; nf++) {
            int c = c0 + wn * 16 + nf * 8 + 2 * t;
            if (m < DIM) {
                if (c < NC)     Zout[(size_t)m * NC + c]     = fmaf(INVN, acc[mf][nf][0], Zin[(size_t)m * NC + c]);
                if (c + 1 < NC) Zout[(size_t)m * NC + c + 1] = fmaf(INVN, acc[mf][nf][1], Zin[(size_t)m * NC + c + 1]);
            }
            if (m + 8 < DIM) {
                if (c < NC)     Zout[(size_t)(m + 8) * NC + c]     = fmaf(INVN, acc[mf][nf][2], Zin[(size_t)(m + 8) * NC + c]);
                if (c + 1 < NC) Zout[(size_t)(m + 8) * NC + c + 1] = fmaf(INVN, acc[mf][nf][3], Zin[(size_t)(m + 8) * NC + c + 1]);
            }
        }
    }
}

// ---------------- launch ----------------
extern "C" void kernel_launch(void* const* d_in, const int* in_sizes, int n_in,
                              void* d_out, int out_size) {
    const float* Z = (const float*)d_in[0];
    const float* P = (const float*)d_in[1];
    const float* Q = (const float*)d_in[2];
    float* out = (float*)d_out;

    float *za, *zb;
    cudaGetSymbolAddress((void**)&za, g_ZA);
    cudaGetSymbolAddress((void**)&zb, g_ZB);

    kernel_init<<<512, 256>>>();

    for (int l = 0; l < 4; l++) {
        const float* zin; float* zout;
        if (l == 0)      { zin = Z;  zout = za; }
        else if (l == 1) { zin = za; zout = zb; }
        else if (l == 2) { zin = zb; zout = za; }
        else             { zin = za; zout = out; }

        kernel_qp  <<<129, 256>>>(zin, Q, P);
        kernel_scan<<<DIM, 256>>>();
        kernel_x   <<<dim3(65, 65), 256>>>();
        kernel_s   <<<33, 256>>>();
        kernel_tb  <<<dim3(33, DIM), 256>>>();
        kernel_u   <<<129, 384>>>(zin, zout);
    }
}

// round 8
// speedup vs baseline: 3.0261x; 1.1994x over previous
#include <cuda_runtime.h>
#include <cuda_bf16.h>
#include <cstdint>

#define DIM   129
#define NC    8193
#define NSEQ  8192
#define NCP   8320          // 65 * 128
#define KP    144           // DIM padded to multiple of 16
#define UCH   32
#define NKCH  (NCP/UCH)     // 260
#define NTC   65
#define ULDA  40            // kernel_u A smem pitch in halves (80B -> conflict-free LDSM)
#define LMBD  0.9f
#define INVN  (1.0f/8192.0f)
#define SZ    (DIM*NC)

// ---------------- device scratch ----------------
__device__ __align__(16) uint16_t g_Zbf[(size_t)KP * NCP];    // Z bf16, [k][m], zero-padded
__device__ __align__(16) uint16_t g_Wbf[(size_t)KP * NCP];    // Q@Z bf16, [d][c], zero-padded
__device__ __align__(16) uint16_t g_Tbf[(size_t)KP * NCP];    // (T*sinv) bf16, [m][k], zero-padded
__device__ __align__(16) uint16_t g_Eb [(size_t)NCP * NCP];   // exp(X) bf16, [r][c]  (~138 MB)
__device__ float    g_Y[SZ];
__device__ float    g_T[SZ];
__device__ float    g_sinv[NC];
__device__ float    g_spart[(size_t)NTC * NCP];
__device__ float    g_ZA[SZ], g_ZB[SZ];

__device__ __forceinline__ void mma16816(float* d, const uint32_t* a, const uint32_t* b) {
    asm volatile(
        "mma.sync.aligned.m16n8k16.row.col.f32.bf16.bf16.f32 "
        "{%0,%1,%2,%3},{%4,%5,%6,%7},{%8,%9},{%0,%1,%2,%3};\n"
        : "+f"(d[0]), "+f"(d[1]), "+f"(d[2]), "+f"(d[3])
        : "r"(a[0]), "r"(a[1]), "r"(a[2]), "r"(a[3]), "r"(b[0]), "r"(b[1]));
}

__device__ __forceinline__ uint32_t cvta_s(const void* p) {
    return (uint32_t)__cvta_generic_to_shared(p);
}
__device__ __forceinline__ void ldsm4(uint32_t* r, uint32_t a) {
    asm volatile("ldmatrix.sync.aligned.m8n8.x4.shared.b16 {%0,%1,%2,%3},[%4];"
                 : "=r"(r[0]), "=r"(r[1]), "=r"(r[2]), "=r"(r[3]) : "r"(a));
}
__device__ __forceinline__ void ldsm4t(uint32_t* r, uint32_t a) {
    asm volatile("ldmatrix.sync.aligned.m8n8.x4.trans.shared.b16 {%0,%1,%2,%3},[%4];"
                 : "=r"(r[0]), "=r"(r[1]), "=r"(r[2]), "=r"(r[3]) : "r"(a));
}

__device__ __forceinline__ uint16_t f2bf(float x) {
    __nv_bfloat16 h = __float2bfloat16(x);
    return reinterpret_cast<uint16_t&>(h);
}

// ---------------- init: zero the padded bf16 operand buffers ----------------
__global__ void kernel_init() {
    size_t n = (size_t)KP * NCP;
    size_t stride = (size_t)gridDim.x * blockDim.x;
    for (size_t j = (size_t)blockIdx.x * blockDim.x + threadIdx.x; j < n; j += stride) {
        g_Zbf[j] = 0; g_Wbf[j] = 0; g_Tbf[j] = 0;
    }
}

// ---------------- kernel 1: W = Q@Z (bf16 out), Y = P@Z (fp32), Zb = bf16(Z) ----------
__global__ __launch_bounds__(256) void kernel_qp(const float* __restrict__ Zin,
                                                 const float* __restrict__ Q,
                                                 const float* __restrict__ P) {
    __shared__ float Zs[DIM][64];
    const int c0 = blockIdx.x * 64;
    const int tid = threadIdx.x;
    const int c = tid & 63;
    const int grp = tid >> 6;
    for (int k = grp; k < DIM; k += 4) {
        float z = (c0 + c < NC) ? Zin[(size_t)k * NC + c0 + c] : 0.f;
        Zs[k][c] = z;
        if (c0 + c < NC) g_Zbf[(size_t)k * NCP + c0 + c] = f2bf(z);
    }
    __syncthreads();
    if (c0 + c < NC) {
        for (int d = grp; d < DIM; d += 4) {
            float aw = 0.f, ay = 0.f;
            const float* qrow = Q + (size_t)d * DIM;
            const float* prow = P + (size_t)d * DIM;
            #pragma unroll 8
            for (int k = 0; k < DIM; k++) {
                float z = Zs[k][c];
                aw = fmaf(qrow[k], z, aw);
                ay = fmaf(prow[k], z, ay);
            }
            g_Wbf[(size_t)d * NCP + c0 + c] = f2bf(aw);
            g_Y[(size_t)d * NC + c0 + c] = ay;
        }
    }
}

// ---------------- kernel 2: backward decayed scan T[j] = Y[j] + lam*T[j+1] ----------
__global__ __launch_bounds__(256) void kernel_scan() {
    const int r = blockIdx.x;
    const int t = threadIdx.x;
    const float* Y = g_Y + (size_t)r * NC;
    float*       T = g_T + (size_t)r * NC;
    const int base = t * 32;

    float s = 0.f;
    #pragma unroll
    for (int u = 31; u >= 0; u--) s = fmaf(s, LMBD, Y[base + u]);

    __shared__ float C[256];
    C[t] = s;
    __syncthreads();

    float f = 1.f;
    #pragma unroll
    for (int i = 0; i < 32; i++) f *= LMBD;

    for (int off = 1; off < 256; off <<= 1) {
        float add = (t + off < 256) ? C[t + off] * f : 0.f;
        __syncthreads();
        C[t] += add;
        __syncthreads();
        f *= f;
    }
    float cur = (t < 255) ? C[t + 1] : 0.f;
    #pragma unroll
    for (int u = 31; u >= 0; u--) {
        cur = fmaf(LMBD, cur, Y[base + u]);
        T[base + u] = cur;
    }
    if (t == 0) T[NSEQ] = 0.f;
}

// ---------------- kernel 3: X = Z^T W (bf16 HMMA + LDSM), exp + Eb + row partials ----
__global__ __launch_bounds__(256, 2) void kernel_x() {
    __shared__ __align__(16) uint16_t As[2][2048];   // [k16][m128], swizzled
    __shared__ __align__(16) uint16_t Bs[2][2048];   // [k16][n128], swizzled
    __shared__ float Ssum[4][128];
    const int bx = blockIdx.x, by = blockIdx.y;
    const int r0 = by * 128, c0 = bx * 128;
    const int tid = threadIdx.x, lane = tid & 31, wid = tid >> 5;
    const int wm = wid >> 2, wn = wid & 3, g = lane >> 2, t = lane & 3;

    float acc[4][4][4] = {};

    // staging: thread -> (k row sk, 16B chunk sc), swizzled chunk ssc
    const int sk = tid >> 4, sc = tid & 15, ssc = sc ^ (sk & 7);
    const uint16_t* gA = g_Zbf + (size_t)sk * NCP + r0 + sc * 8;
    const uint16_t* gB = g_Wbf + (size_t)sk * NCP + c0 + sc * 8;
    uint16_t* pA = &As[0][sk * 128 + ssc * 8];
    uint16_t* pB = &Bs[0][sk * 128 + ssc * 8];

    // per-lane ldmatrix constants
    const int krA = ((lane >> 4) << 3) + (lane & 7);   // A: mats 0,1 -> k0-7; 2,3 -> k8-15
    const int mlow = (lane >> 3) & 1;                  // A: m-chunk low bit
    const int krB = (((lane >> 3) & 1) << 3) + (lane & 7); // B: mats 0,2 -> k0-7; 1,3 -> k8-15
    const int nco = lane >> 4;                         // B: n-chunk offset
    const uint32_t baseA = cvta_s(As) + krA * 256;
    const uint32_t baseB = cvta_s(Bs) + krB * 256;
    const int xorA = krA & 7, xorB = krB & 7;

    // prologue: chunk 0
    {
        uint4 va = *reinterpret_cast<const uint4*>(gA);
        uint4 vb = *reinterpret_cast<const uint4*>(gB);
        *reinterpret_cast<uint4*>(pA) = va;
        *reinterpret_cast<uint4*>(pB) = vb;
    }
    __syncthreads();

    #pragma unroll
    for (int ck = 0; ck < 9; ck++) {
        uint4 va, vb;
        if (ck < 8) {
            va = *reinterpret_cast<const uint4*>(gA + (size_t)(ck + 1) * 16 * NCP);
            vb = *reinterpret_cast<const uint4*>(gB + (size_t)(ck + 1) * 16 * NCP);
        }
        const int bo = (ck & 1) * 4096;   // byte offset of current buffer
        uint32_t a[4][4], b[4][2];
        #pragma unroll
        for (int mf = 0; mf < 4; mf++)
            ldsm4t(a[mf], baseA + bo + (((wm * 8 + mf * 2 + mlow) ^ xorA) << 4));
        {
            uint32_t r[4];
            ldsm4t(r, baseB + bo + (((wn * 4 + 0 + nco) ^ xorB) << 4));
            b[0][0] = r[0]; b[0][1] = r[1]; b[1][0] = r[2]; b[1][1] = r[3];
            ldsm4t(r, baseB + bo + (((wn * 4 + 2 + nco) ^ xorB) << 4));
            b[2][0] = r[0]; b[2][1] = r[1]; b[3][0] = r[2]; b[3][1] = r[3];
        }
        #pragma unroll
        for (int mf = 0; mf < 4; mf++)
            #pragma unroll
            for (int nf = 0; nf < 4; nf++)
                mma16816(acc[mf][nf], a[mf], b[nf]);

        if (ck < 8) {
            __syncthreads();
            const int so = ((ck + 1) & 1) * 2048;  // element offset
            *reinterpret_cast<uint4*>(pA + so) = va;
            *reinterpret_cast<uint4*>(pB + so) = vb;
            __syncthreads();
        }
    }

    // epilogue: exp, store bf16, masked row partial sums
    float rs[4][2];
    #pragma unroll
    for (int mf = 0; mf < 4; mf++) { rs[mf][0] = 0.f; rs[mf][1] = 0.f; }
    #pragma unroll
    for (int mf = 0; mf < 4; mf++) {
        int rg = r0 + wm * 64 + mf * 16 + g;
        #pragma unroll
        for (int nf = 0; nf < 4; nf++) {
            int cb = c0 + wn * 32 + nf * 8 + 2 * t;
            float e0 = __expf(acc[mf][nf][0]);
            float e1 = __expf(acc[mf][nf][1]);
            float e2 = __expf(acc[mf][nf][2]);
            float e3 = __expf(acc[mf][nf][3]);
            __nv_bfloat162 p01 = __floats2bfloat162_rn(e0, e1);
            __nv_bfloat162 p23 = __floats2bfloat162_rn(e2, e3);
            *reinterpret_cast<uint32_t*>(&g_Eb[(size_t)rg * NCP + cb]) = reinterpret_cast<uint32_t&>(p01);
            *reinterpret_cast<uint32_t*>(&g_Eb[(size_t)(rg + 8) * NCP + cb]) = reinterpret_cast<uint32_t&>(p23);
            float m0 = (cb < NC) ? 1.f : 0.f;
            float m1 = (cb + 1 < NC) ? 1.f : 0.f;
            rs[mf][0] += e0 * m0 + e1 * m1;
            rs[mf][1] += e2 * m0 + e3 * m1;
        }
    }
    #pragma unroll
    for (int mf = 0; mf < 4; mf++)
        #pragma unroll
        for (int h = 0; h < 2; h++) {
            float v = rs[mf][h];
            v += __shfl_xor_sync(0xffffffffu, v, 1);
            v += __shfl_xor_sync(0xffffffffu, v, 2);
            rs[mf][h] = v;
        }
    if (t == 0) {
        #pragma unroll
        for (int mf = 0; mf < 4; mf++) {
            Ssum[wn][wm * 64 + mf * 16 + g]     = rs[mf][0];
            Ssum[wn][wm * 64 + mf * 16 + g + 8] = rs[mf][1];
        }
    }
    __syncthreads();
    if (tid < 128) {
        float p = Ssum[0][tid] + Ssum[1][tid] + Ssum[2][tid] + Ssum[3][tid];
        g_spart[(size_t)bx * NCP + r0 + tid] = p;
    }
}

// ---------------- kernel 4: sinv ----------------
__global__ __launch_bounds__(256) void kernel_s() {
    int r = blockIdx.x * 256 + threadIdx.x;
    if (r < NC) {
        float s = 0.f;
        #pragma unroll 5
        for (int tb = 0; tb < NTC; tb++) s += g_spart[(size_t)tb * NCP + r];
        g_sinv[r] = 1.0f / s;
    }
}

// ---------------- kernel 5: Tb = bf16(T * sinv) ----------------
__global__ __launch_bounds__(256) void kernel_tb() {
    int k = blockIdx.x * 256 + threadIdx.x;
    int m = blockIdx.y;
    if (k < NC) {
        float v = g_T[(size_t)m * NC + k] * g_sinv[k];
        g_Tbf[(size_t)m * NCP + k] = f2bf(v);
    }
}

// ---------------- kernel 6: Zout = Zin + invn*(Tb @ Eb), bf16 HMMA + LDSM -----------
__global__ __launch_bounds__(384) void kernel_u(const float* __restrict__ Zin,
                                                float* __restrict__ Zout) {
    __shared__ __align__(16) uint16_t As[2][KP * ULDA];  // [m144][k32], pitch 40 halves
    __shared__ __align__(16) uint16_t Bs[2][32 * 64];    // [k32][n64], swizzled
    const int c0 = blockIdx.x * 64;
    const int tid = threadIdx.x, lane = tid & 31, wid = tid >> 5;
    const int wm = wid >> 2, wn = wid & 3, g = lane >> 2, t = lane & 3;

    float acc[3][2][4] = {};

    // staging coords
    const int am  = tid >> 2,          ac  = tid & 3;          // A part 1: 384 of 576
    const int am2 = (tid + 384) >> 2,  ac2 = (tid + 384) & 3;  // A part 2: 192 of 576
    const bool a2v = (tid + 384) < 576;
    const int bk = tid >> 3, bc = tid & 7, bsc = bc ^ (bk & 7); // B: first 256 threads
    const bool bv = tid < 256;

    // per-lane ldmatrix constants
    const int mr  = (((lane >> 3) & 1) << 3) + (lane & 7);  // A row within 16
    const int kco = lane >> 4;                              // A k-chunk offset
    const int krB = (((lane >> 3) & 1) << 3) + (lane & 7);  // B k row within 16
    const int nco = lane >> 4;                              // B n-chunk offset
    const uint32_t baseA = cvta_s(As);
    const uint32_t baseB = cvta_s(Bs) + krB * 128;
    const int xorB = krB & 7;

    // prologue: stage chunk 0
    {
        *reinterpret_cast<uint4*>(&As[0][am * ULDA + ac * 8]) =
            *reinterpret_cast<const uint4*>(&g_Tbf[(size_t)am * NCP + ac * 8]);
        if (a2v)
            *reinterpret_cast<uint4*>(&As[0][am2 * ULDA + ac2 * 8]) =
                *reinterpret_cast<const uint4*>(&g_Tbf[(size_t)am2 * NCP + ac2 * 8]);
        if (bv)
            *reinterpret_cast<uint4*>(&Bs[0][bk * 64 + bsc * 8]) =
                *reinterpret_cast<const uint4*>(&g_Eb[(size_t)bk * NCP + c0 + bc * 8]);
    }
    __syncthreads();

    for (int ck = 0; ck < NKCH; ck++) {
        uint4 va0, va1, vb;
        if (ck + 1 < NKCH) {
            const int kk = (ck + 1) * UCH;
            va0 = *reinterpret_cast<const uint4*>(&g_Tbf[(size_t)am * NCP + kk + ac * 8]);
            if (a2v)
                va1 = *reinterpret_cast<const uint4*>(&g_Tbf[(size_t)am2 * NCP + kk + ac2 * 8]);
            if (bv)
                vb = *reinterpret_cast<const uint4*>(&g_Eb[(size_t)(kk + bk) * NCP + c0 + bc * 8]);
        }
        const int boA = (ck & 1) * (KP * ULDA * 2);   // bytes
        const int boB = (ck & 1) * (32 * 64 * 2);
        #pragma unroll
        for (int ks = 0; ks < 2; ks++) {
            uint32_t a[3][4], b[2][2];
            #pragma unroll
            for (int mf = 0; mf < 3; mf++)
                ldsm4(a[mf], baseA + boA + (wm * 48 + mf * 16 + mr) * (ULDA * 2)
                                         + (ks * 2 + kco) * 16);
            {
                uint32_t r[4];
                ldsm4t(r, baseB + boB + ks * 16 * 128 + (((wn * 2 + nco) ^ xorB) << 4));
                b[0][0] = r[0]; b[0][1] = r[1]; b[1][0] = r[2]; b[1][1] = r[3];
            }
            #pragma unroll
            for (int mf = 0; mf < 3; mf++)
                #pragma unroll
                for (int nf = 0; nf < 2; nf++)
                    mma16816(acc[mf][nf], a[mf], b[nf]);
        }
        if (ck + 1 < NKCH) {
            __syncthreads();
            const int s = (ck + 1) & 1;
            *reinterpret_cast<uint4*>(&As[s][am * ULDA + ac * 8]) = va0;
            if (a2v) *reinterpret_cast<uint4*>(&As[s][am2 * ULDA + ac2 * 8]) = va1;
            if (bv)  *reinterpret_cast<uint4*>(&Bs[s][bk * 64 + bsc * 8]) = vb;
            __syncthreads();
        }
    }

    // epilogue: residual + scale
    #pragma unroll
    for (int mf = 0; mf < 3; mf++) {
        int m = wm * 48 + mf * 16 + g;
        #pragma unroll
        for (int nf = 0; nf < 2; nf++) {
            int c = c0 + wn * 16 + nf * 8 + 2 * t;
            if (m < DIM) {
                if (c < NC)     Zout[(size_t)m * NC + c]     = fmaf(INVN, acc[mf][nf][0], Zin[(size_t)m * NC + c]);
                if (c + 1 < NC) Zout[(size_t)m * NC + c + 1] = fmaf(INVN, acc[mf][nf][1], Zin[(size_t)m * NC + c + 1]);
            }
            if (m + 8 < DIM) {
                if (c < NC)     Zout[(size_t)(m + 8) * NC + c]     = fmaf(INVN, acc[mf][nf][2], Zin[(size_t)(m + 8) * NC + c]);
                if (c + 1 < NC) Zout[(size_t)(m + 8) * NC + c + 1] = fmaf(INVN, acc[mf][nf][3], Zin[(size_t)(m + 8) * NC + c + 1]);
            }
        }
    }
}

// ---------------- launch ----------------
extern "C" void kernel_launch(void* const* d_in, const int* in_sizes, int n_in,
                              void* d_out, int out_size) {
    const float* Z = (const float*)d_in[0];
    const float* P = (const float*)d_in[1];
    const float* Q = (const float*)d_in[2];
    float* out = (float*)d_out;

    float *za, *zb;
    cudaGetSymbolAddress((void**)&za, g_ZA);
    cudaGetSymbolAddress((void**)&zb, g_ZB);

    kernel_init<<<512, 256>>>();

    for (int l = 0; l < 4; l++) {
        const float* zin; float* zout;
        if (l == 0)      { zin = Z;  zout = za; }
        else if (l == 1) { zin = za; zout = zb; }
        else if (l == 2) { zin = zb; zout = za; }
        else             { zin = za; zout = out; }

        kernel_qp  <<<129, 256>>>(zin, Q, P);
        kernel_scan<<<DIM, 256>>>();
        kernel_x   <<<dim3(65, 65), 256>>>();
        kernel_s   <<<33, 256>>>();
        kernel_tb  <<<dim3(33, DIM), 256>>>();
        kernel_u   <<<129, 384>>>(zin, zout);
    }
}

// round 12
// speedup vs baseline: 3.7383x; 1.2354x over previous
#include <cuda_runtime.h>
#include <cuda_bf16.h>
#include <cstdint>

#define DIM   129
#define NC    8193
#define NSEQ  8192
#define NCP   8320          // 65 * 128
#define KP    144           // DIM padded to multiple of 16
#define UCH   32
#define NKCH  (NCP/UCH)     // 260
#define NSPL  10            // K-splits for kernel_u
#define CPS   (NKCH/NSPL)   // 26 chunks per split
#define NTC   65
#define ULDA  40            // kernel_u A smem pitch in halves (80B -> conflict-free LDSM)
#define LMBD  0.9f
#define INVN  (1.0f/8192.0f)
#define SZ    (DIM*NC)

// ---------------- device scratch ----------------
__device__ __align__(16) uint16_t g_Zbf[(size_t)KP * NCP];    // Z bf16, [k][m], zero-padded
__device__ __align__(16) uint16_t g_Wbf[(size_t)KP * NCP];    // Q@Z bf16, [d][c], zero-padded
__device__ __align__(16) uint16_t g_Tbf[(size_t)KP * NCP];    // (T*sinv) bf16, [m][k], zero-padded
__device__ __align__(16) uint16_t g_Eb [(size_t)NCP * NCP];   // exp(X) bf16, [r][c]  (~138 MB)
__device__ float    g_Y[SZ];
__device__ float    g_T[SZ];
__device__ float    g_sinv[NC];
__device__ float    g_spart[(size_t)NTC * NCP];
__device__ float    g_Up[(size_t)NSPL * SZ];                  // fp32 K-split partials (~42 MB)
__device__ float    g_ZA[SZ], g_ZB[SZ];

__device__ __forceinline__ void mma16816(float* d, const uint32_t* a, const uint32_t* b) {
    asm volatile(
        "mma.sync.aligned.m16n8k16.row.col.f32.bf16.bf16.f32 "
        "{%0,%1,%2,%3},{%4,%5,%6,%7},{%8,%9},{%0,%1,%2,%3};\n"
        : "+f"(d[0]), "+f"(d[1]), "+f"(d[2]), "+f"(d[3])
        : "r"(a[0]), "r"(a[1]), "r"(a[2]), "r"(a[3]), "r"(b[0]), "r"(b[1]));
}

__device__ __forceinline__ uint32_t cvta_s(const void* p) {
    return (uint32_t)__cvta_generic_to_shared(p);
}
__device__ __forceinline__ void ldsm4(uint32_t* r, uint32_t a) {
    asm volatile("ldmatrix.sync.aligned.m8n8.x4.shared.b16 {%0,%1,%2,%3},[%4];"
                 : "=r"(r[0]), "=r"(r[1]), "=r"(r[2]), "=r"(r[3]) : "r"(a));
}
__device__ __forceinline__ void ldsm4t(uint32_t* r, uint32_t a) {
    asm volatile("ldmatrix.sync.aligned.m8n8.x4.trans.shared.b16 {%0,%1,%2,%3},[%4];"
                 : "=r"(r[0]), "=r"(r[1]), "=r"(r[2]), "=r"(r[3]) : "r"(a));
}

__device__ __forceinline__ uint16_t f2bf(float x) {
    __nv_bfloat16 h = __float2bfloat16(x);
    return reinterpret_cast<uint16_t&>(h);
}

// ---------------- init: zero the padded bf16 operand buffers ----------------
__global__ void kernel_init() {
    size_t n = (size_t)KP * NCP;
    size_t stride = (size_t)gridDim.x * blockDim.x;
    for (size_t j = (size_t)blockIdx.x * blockDim.x + threadIdx.x; j < n; j += stride) {
        g_Zbf[j] = 0; g_Wbf[j] = 0; g_Tbf[j] = 0;
    }
}

// ---------------- kernel 1: W = Q@Z (bf16 out), Y = P@Z (fp32), Zb = bf16(Z) ----------
__global__ __launch_bounds__(256) void kernel_qp(const float* __restrict__ Zin,
                                                 const float* __restrict__ Q,
                                                 const float* __restrict__ P) {
    __shared__ float Zs[DIM][64];
    const int c0 = blockIdx.x * 64;
    const int tid = threadIdx.x;
    const int c = tid & 63;
    const int grp = tid >> 6;
    for (int k = grp; k < DIM; k += 4) {
        float z = (c0 + c < NC) ? Zin[(size_t)k * NC + c0 + c] : 0.f;
        Zs[k][c] = z;
        if (c0 + c < NC) g_Zbf[(size_t)k * NCP + c0 + c] = f2bf(z);
    }
    __syncthreads();
    if (c0 + c < NC) {
        for (int d = grp; d < DIM; d += 4) {
            float aw = 0.f, ay = 0.f;
            const float* qrow = Q + (size_t)d * DIM;
            const float* prow = P + (size_t)d * DIM;
            #pragma unroll 8
            for (int k = 0; k < DIM; k++) {
                float z = Zs[k][c];
                aw = fmaf(qrow[k], z, aw);
                ay = fmaf(prow[k], z, ay);
            }
            g_Wbf[(size_t)d * NCP + c0 + c] = f2bf(aw);
            g_Y[(size_t)d * NC + c0 + c] = ay;
        }
    }
}

// ---------------- kernel 2: backward decayed scan T[j] = Y[j] + lam*T[j+1] ----------
__global__ __launch_bounds__(256) void kernel_scan() {
    const int r = blockIdx.x;
    const int t = threadIdx.x;
    const float* Y = g_Y + (size_t)r * NC;
    float*       T = g_T + (size_t)r * NC;
    const int base = t * 32;

    float s = 0.f;
    #pragma unroll
    for (int u = 31; u >= 0; u--) s = fmaf(s, LMBD, Y[base + u]);

    __shared__ float C[256];
    C[t] = s;
    __syncthreads();

    float f = 1.f;
    #pragma unroll
    for (int i = 0; i < 32; i++) f *= LMBD;

    for (int off = 1; off < 256; off <<= 1) {
        float add = (t + off < 256) ? C[t + off] * f : 0.f;
        __syncthreads();
        C[t] += add;
        __syncthreads();
        f *= f;
    }
    float cur = (t < 255) ? C[t + 1] : 0.f;
    #pragma unroll
    for (int u = 31; u >= 0; u--) {
        cur = fmaf(LMBD, cur, Y[base + u]);
        T[base + u] = cur;
    }
    if (t == 0) T[NSEQ] = 0.f;
}

// ---------------- kernel 3: X = Z^T W (bf16 HMMA + LDSM), exp + Eb + row partials ----
__global__ __launch_bounds__(256, 2) void kernel_x() {
    __shared__ __align__(16) uint16_t As[2][2048];   // [k16][m128], swizzled
    __shared__ __align__(16) uint16_t Bs[2][2048];   // [k16][n128], swizzled
    __shared__ float Ssum[4][128];
    const int bx = blockIdx.x, by = blockIdx.y;
    const int r0 = by * 128, c0 = bx * 128;
    const int tid = threadIdx.x, lane = tid & 31, wid = tid >> 5;
    const int wm = wid >> 2, wn = wid & 3, g = lane >> 2, t = lane & 3;

    float acc[4][4][4] = {};

    // staging: thread -> (k row sk, 16B chunk sc), swizzled chunk ssc
    const int sk = tid >> 4, sc = tid & 15, ssc = sc ^ (sk & 7);
    const uint16_t* gA = g_Zbf + (size_t)sk * NCP + r0 + sc * 8;
    const uint16_t* gB = g_Wbf + (size_t)sk * NCP + c0 + sc * 8;
    uint16_t* pA = &As[0][sk * 128 + ssc * 8];
    uint16_t* pB = &Bs[0][sk * 128 + ssc * 8];

    // per-lane ldmatrix constants
    const int krA = ((lane >> 4) << 3) + (lane & 7);   // A: mats 0,1 -> k0-7; 2,3 -> k8-15
    const int mlow = (lane >> 3) & 1;                  // A: m-chunk low bit
    const int krB = (((lane >> 3) & 1) << 3) + (lane & 7); // B: mats 0,2 -> k0-7; 1,3 -> k8-15
    const int nco = lane >> 4;                         // B: n-chunk offset
    const uint32_t baseA = cvta_s(As) + krA * 256;
    const uint32_t baseB = cvta_s(Bs) + krB * 256;
    const int xorA = krA & 7, xorB = krB & 7;

    // prologue: chunk 0
    {
        uint4 va = *reinterpret_cast<const uint4*>(gA);
        uint4 vb = *reinterpret_cast<const uint4*>(gB);
        *reinterpret_cast<uint4*>(pA) = va;
        *reinterpret_cast<uint4*>(pB) = vb;
    }
    __syncthreads();

    #pragma unroll
    for (int ck = 0; ck < 9; ck++) {
        uint4 va, vb;
        if (ck < 8) {
            va = *reinterpret_cast<const uint4*>(gA + (size_t)(ck + 1) * 16 * NCP);
            vb = *reinterpret_cast<const uint4*>(gB + (size_t)(ck + 1) * 16 * NCP);
        }
        const int bo = (ck & 1) * 4096;   // byte offset of current buffer
        uint32_t a[4][4], b[4][2];
        #pragma unroll
        for (int mf = 0; mf < 4; mf++)
            ldsm4t(a[mf], baseA + bo + (((wm * 8 + mf * 2 + mlow) ^ xorA) << 4));
        {
            uint32_t r[4];
            ldsm4t(r, baseB + bo + (((wn * 4 + 0 + nco) ^ xorB) << 4));
            b[0][0] = r[0]; b[0][1] = r[1]; b[1][0] = r[2]; b[1][1] = r[3];
            ldsm4t(r, baseB + bo + (((wn * 4 + 2 + nco) ^ xorB) << 4));
            b[2][0] = r[0]; b[2][1] = r[1]; b[3][0] = r[2]; b[3][1] = r[3];
        }
        #pragma unroll
        for (int mf = 0; mf < 4; mf++)
            #pragma unroll
            for (int nf = 0; nf < 4; nf++)
                mma16816(acc[mf][nf], a[mf], b[nf]);

        if (ck < 8) {
            __syncthreads();
            const int so = ((ck + 1) & 1) * 2048;  // element offset
            *reinterpret_cast<uint4*>(pA + so) = va;
            *reinterpret_cast<uint4*>(pB + so) = vb;
            __syncthreads();
        }
    }

    // epilogue: exp, store bf16, masked row partial sums
    float rs[4][2];
    #pragma unroll
    for (int mf = 0; mf < 4; mf++) { rs[mf][0] = 0.f; rs[mf][1] = 0.f; }
    #pragma unroll
    for (int mf = 0; mf < 4; mf++) {
        int rg = r0 + wm * 64 + mf * 16 + g;
        #pragma unroll
        for (int nf = 0; nf < 4; nf++) {
            int cb = c0 + wn * 32 + nf * 8 + 2 * t;
            float e0 = __expf(acc[mf][nf][0]);
            float e1 = __expf(acc[mf][nf][1]);
            float e2 = __expf(acc[mf][nf][2]);
            float e3 = __expf(acc[mf][nf][3]);
            __nv_bfloat162 p01 = __floats2bfloat162_rn(e0, e1);
            __nv_bfloat162 p23 = __floats2bfloat162_rn(e2, e3);
            *reinterpret_cast<uint32_t*>(&g_Eb[(size_t)rg * NCP + cb]) = reinterpret_cast<uint32_t&>(p01);
            *reinterpret_cast<uint32_t*>(&g_Eb[(size_t)(rg + 8) * NCP + cb]) = reinterpret_cast<uint32_t&>(p23);
            float m0 = (cb < NC) ? 1.f : 0.f;
            float m1 = (cb + 1 < NC) ? 1.f : 0.f;
            rs[mf][0] += e0 * m0 + e1 * m1;
            rs[mf][1] += e2 * m0 + e3 * m1;
        }
    }
    #pragma unroll
    for (int mf = 0; mf < 4; mf++)
        #pragma unroll
        for (int h = 0; h < 2; h++) {
            float v = rs[mf][h];
            v += __shfl_xor_sync(0xffffffffu, v, 1);
            v += __shfl_xor_sync(0xffffffffu, v, 2);
            rs[mf][h] = v;
        }
    if (t == 0) {
        #pragma unroll
        for (int mf = 0; mf < 4; mf++) {
            Ssum[wn][wm * 64 + mf * 16 + g]     = rs[mf][0];
            Ssum[wn][wm * 64 + mf * 16 + g + 8] = rs[mf][1];
        }
    }
    __syncthreads();
    if (tid < 128) {
        float p = Ssum[0][tid] + Ssum[1][tid] + Ssum[2][tid] + Ssum[3][tid];
        g_spart[(size_t)bx * NCP + r0 + tid] = p;
    }
}

// ---------------- kernel 4: sinv ----------------
__global__ __launch_bounds__(256) void kernel_s() {
    int r = blockIdx.x * 256 + threadIdx.x;
    if (r < NC) {
        float s = 0.f;
        #pragma unroll 5
        for (int tb = 0; tb < NTC; tb++) s += g_spart[(size_t)tb * NCP + r];
        g_sinv[r] = 1.0f / s;
    }
}

// ---------------- kernel 5: Tb = bf16(T * sinv) ----------------
__global__ __launch_bounds__(256) void kernel_tb() {
    int k = blockIdx.x * 256 + threadIdx.x;
    int m = blockIdx.y;
    if (k < NC) {
        float v = g_T[(size_t)m * NC + k] * g_sinv[k];
        g_Tbf[(size_t)m * NCP + k] = f2bf(v);
    }
}

// ---------------- kernel 6: Up[s] = Tb @ Eb over K-slice s (bf16 HMMA + LDSM) -------
__global__ __launch_bounds__(384) void kernel_u() {
    __shared__ __align__(16) uint16_t As[2][KP * ULDA];  // [m144][k32], pitch 40 halves
    __shared__ __align__(16) uint16_t Bs[2][32 * 64];    // [k32][n64], swizzled
    const int c0 = blockIdx.x * 64;
    const int ckb = blockIdx.y * CPS;                    // first chunk of this K-split
    const int tid = threadIdx.x, lane = tid & 31, wid = tid >> 5;
    const int wm = wid >> 2, wn = wid & 3, g = lane >> 2, t = lane & 3;

    float acc[3][2][4] = {};

    // staging coords
    const int am  = tid >> 2,          ac  = tid & 3;          // A part 1: 384 of 576
    const int am2 = (tid + 384) >> 2,  ac2 = (tid + 384) & 3;  // A part 2: 192 of 576
    const bool a2v = (tid + 384) < 576;
    const int bk = tid >> 3, bc = tid & 7, bsc = bc ^ (bk & 7); // B: first 256 threads
    const bool bv = tid < 256;

    // per-lane ldmatrix constants
    const int mr  = (((lane >> 3) & 1) << 3) + (lane & 7);  // A row within 16
    const int kco = lane >> 4;                              // A k-chunk offset
    const int krB = (((lane >> 3) & 1) << 3) + (lane & 7);  // B k row within 16
    const int nco = lane >> 4;                              // B n-chunk offset
    const uint32_t baseA = cvta_s(As);
    const uint32_t baseB = cvta_s(Bs) + krB * 128;
    const int xorB = krB & 7;

    // prologue: stage chunk ckb
    {
        const int kk = ckb * UCH;
        *reinterpret_cast<uint4*>(&As[0][am * ULDA + ac * 8]) =
            *reinterpret_cast<const uint4*>(&g_Tbf[(size_t)am * NCP + kk + ac * 8]);
        if (a2v)
            *reinterpret_cast<uint4*>(&As[0][am2 * ULDA + ac2 * 8]) =
                *reinterpret_cast<const uint4*>(&g_Tbf[(size_t)am2 * NCP + kk + ac2 * 8]);
        if (bv)
            *reinterpret_cast<uint4*>(&Bs[0][bk * 64 + bsc * 8]) =
                *reinterpret_cast<const uint4*>(&g_Eb[(size_t)(kk + bk) * NCP + c0 + bc * 8]);
    }
    __syncthreads();

    for (int ci = 0; ci < CPS; ci++) {
        uint4 va0, va1, vb;
        if (ci + 1 < CPS) {
            const int kk = (ckb + ci + 1) * UCH;
            va0 = *reinterpret_cast<const uint4*>(&g_Tbf[(size_t)am * NCP + kk + ac * 8]);
            if (a2v)
                va1 = *reinterpret_cast<const uint4*>(&g_Tbf[(size_t)am2 * NCP + kk + ac2 * 8]);
            if (bv)
                vb = *reinterpret_cast<const uint4*>(&g_Eb[(size_t)(kk + bk) * NCP + c0 + bc * 8]);
        }
        const int boA = (ci & 1) * (KP * ULDA * 2);   // bytes
        const int boB = (ci & 1) * (32 * 64 * 2);
        #pragma unroll
        for (int ks = 0; ks < 2; ks++) {
            uint32_t a[3][4], b[2][2];
            #pragma unroll
            for (int mf = 0; mf < 3; mf++)
                ldsm4(a[mf], baseA + boA + (wm * 48 + mf * 16 + mr) * (ULDA * 2)
                                         + (ks * 2 + kco) * 16);
            {
                uint32_t r[4];
                ldsm4t(r, baseB + boB + ks * 16 * 128 + (((wn * 2 + nco) ^ xorB) << 4));
                b[0][0] = r[0]; b[0][1] = r[1]; b[1][0] = r[2]; b[1][1] = r[3];
            }
            #pragma unroll
            for (int mf = 0; mf < 3; mf++)
                #pragma unroll
                for (int nf = 0; nf < 2; nf++)
                    mma16816(acc[mf][nf], a[mf], b[nf]);
        }
        if (ci + 1 < CPS) {
            __syncthreads();
            const int s = (ci + 1) & 1;
            *reinterpret_cast<uint4*>(&As[s][am * ULDA + ac * 8]) = va0;
            if (a2v) *reinterpret_cast<uint4*>(&As[s][am2 * ULDA + ac2 * 8]) = va1;
            if (bv)  *reinterpret_cast<uint4*>(&Bs[s][bk * 64 + bsc * 8]) = vb;
            __syncthreads();
        }
    }

    // epilogue: write fp32 partial
    float* U = g_Up + (size_t)blockIdx.y * SZ;
    #pragma unroll
    for (int mf = 0; mf < 3; mf++) {
        int m = wm * 48 + mf * 16 + g;
        #pragma unroll
        for (int nf = 0; nf < 2; nf++) {
            int c = c0 + wn * 16 + nf * 8 + 2 * t;
            if (m < DIM) {
                if (c < NC)     U[(size_t)m * NC + c]     = acc[mf][nf][0];
                if (c + 1 < NC) U[(size_t)m * NC + c + 1] = acc[mf][nf][1];
            }
            if (m + 8 < DIM) {
                if (c < NC)     U[(size_t)(m + 8) * NC + c]     = acc[mf][nf][2];
                if (c + 1 < NC) U[(size_t)(m + 8) * NC + c + 1] = acc[mf][nf][3];
            }
        }
    }
}

// ---------------- kernel 7: Zout = Zin + invn * sum_s Up[s] -------------------------
__global__ __launch_bounds__(256) void kernel_fin(const float* __restrict__ Zin,
                                                  float* __restrict__ Zout) {
    int i = blockIdx.x * 256 + threadIdx.x;
    if (i < SZ) {
        float u = 0.f;
        #pragma unroll
        for (int s = 0; s < NSPL; s++) u += g_Up[(size_t)s * SZ + i];
        Zout[i] = fmaf(INVN, u, Zin[i]);
    }
}

// ---------------- launch ----------------
extern "C" void kernel_launch(void* const* d_in, const int* in_sizes, int n_in,
                              void* d_out, int out_size) {
    const float* Z = (const float*)d_in[0];
    const float* P = (const float*)d_in[1];
    const float* Q = (const float*)d_in[2];
    float* out = (float*)d_out;

    float *za, *zb;
    cudaGetSymbolAddress((void**)&za, g_ZA);
    cudaGetSymbolAddress((void**)&zb, g_ZB);

    kernel_init<<<512, 256>>>();

    for (int l = 0; l < 4; l++) {
        const float* zin; float* zout;
        if (l == 0)      { zin = Z;  zout = za; }
        else if (l == 1) { zin = za; zout = zb; }
        else if (l == 2) { zin = zb; zout = za; }
        else             { zin = za; zout = out; }

        kernel_qp  <<<129, 256>>>(zin, Q, P);
        kernel_scan<<<DIM, 256>>>();
        kernel_x   <<<dim3(65, 65), 256>>>();
        kernel_s   <<<33, 256>>>();
        kernel_tb  <<<dim3(33, DIM), 256>>>();
        kernel_u   <<<dim3(129, NSPL), 384>>>();
        kernel_fin <<<(SZ + 255) / 256, 256>>>(zin, zout);
    }
}